// round 9
// baseline (speedup 1.0000x reference)
#include <cuda_runtime.h>
#include <cuda_fp16.h>
#include <cstdint>

// Problem dims
#define S_LEN 1024
#define BATCH 64
#define IDIM  512
#define HDIM  2048
#define ODIM  512
#define MTOT  (S_LEN * BATCH)   // 65536

// ---------------------------------------------------------------------------
// Device scratch (no cudaMalloc allowed)
// ---------------------------------------------------------------------------
__device__ __half g_Xh[(size_t)MTOT * IDIM];        // 64 MB   fp16 X
__device__ __half g_Wh[(size_t)HDIM * IDIM];        // 2 MB    fp16 W_ih
__device__ __half g_uh[(size_t)MTOT * HDIM];        // 256 MB  u (fp16)
__device__ float  g_h [(size_t)BATCH * HDIM];       // 512 KB  h_final[b][h]
__device__ float  g_part[(size_t)32 * BATCH * ODIM];// 4 MB    split-K partials

// ---------------------------------------------------------------------------
// Helpers
// ---------------------------------------------------------------------------
__device__ __forceinline__ void cp_async16(uint32_t saddr, const void* gptr) {
    asm volatile("cp.async.cg.shared.global [%0], [%1], 16;\n"
                 :: "r"(saddr), "l"(gptr) : "memory");
}
#define CP_COMMIT() asm volatile("cp.async.commit_group;\n" ::: "memory")
#define CP_WAIT(N)  asm volatile("cp.async.wait_group %0;\n" :: "n"(N) : "memory")

struct alignas(16) H8 { __half2 a, b, c, d; };

// ---------------------------------------------------------------------------
// Kernel 1: fused fp32 -> fp16 conversion prepass (X then W in one grid)
// ---------------------------------------------------------------------------
#define NX_H8 (MTOT * IDIM / 8)          // 4,194,304
#define NW_H8 (HDIM * IDIM / 8)          // 131,072

__global__ void cvt_kernel(const float4* __restrict__ X,
                           const float4* __restrict__ W) {
    int i = blockIdx.x * blockDim.x + threadIdx.x;
    const float4* src;
    H8* dst;
    int j;
    if (i < NX_H8) {
        src = X;  dst = reinterpret_cast<H8*>(g_Xh);  j = i;
    } else {
        src = W;  dst = reinterpret_cast<H8*>(g_Wh);  j = i - NX_H8;
    }
    float4 v0 = src[2 * j], v1 = src[2 * j + 1];
    H8 o;
    o.a = __floats2half2_rn(v0.x, v0.y);
    o.b = __floats2half2_rn(v0.z, v0.w);
    o.c = __floats2half2_rn(v1.x, v1.y);
    o.d = __floats2half2_rn(v1.z, v1.w);
    dst[j] = o;
}

// ---------------------------------------------------------------------------
// Kernel 2: u = Xh @ Wh^T via mma.sync.m16n8k16 (FROZEN R5 core, ~280 TF/s).
// Launched 4x with an N-chunk offset so scans of finished chunks overlap
// the remaining GEMM chunks via graph fork/join.
// ---------------------------------------------------------------------------
#define BM 128
#define BN 128
#define BKH 32
#define KTILES (IDIM / BKH)        // 16
#define NSTG 3
#define LDAH 40
#define STAGE_HALFS (BM * LDAH)

__global__ __launch_bounds__(256, 2) void gemm_u_kernel(int n_base) {
    __shared__ __half sA[NSTG][STAGE_HALFS];
    __shared__ __half sB[NSTG][STAGE_HALFS];

    const int tid  = threadIdx.x;
    const int lane = tid & 31;
    const int warp = tid >> 5;
    const int wm   = warp >> 1;
    const int wn   = warp & 1;
    const int g    = lane >> 2;
    const int tg   = lane & 3;

    const int m0 = blockIdx.y * BM;
    const int n0 = n_base + blockIdx.x * BN;

    const uint32_t sA_base = (uint32_t)__cvta_generic_to_shared(&sA[0][0]);
    const uint32_t sB_base = (uint32_t)__cvta_generic_to_shared(&sB[0][0]);

    float c[2][8][4];
#pragma unroll
    for (int mi = 0; mi < 2; mi++)
#pragma unroll
        for (int ni = 0; ni < 8; ni++)
#pragma unroll
            for (int r = 0; r < 4; r++) c[mi][ni][r] = 0.0f;

    auto loadAB = [&](int stage, int kt) {
#pragma unroll
        for (int i = 0; i < 2; i++) {
            int lin = tid + i * 256;
            int row = lin >> 2, c16 = lin & 3;
            cp_async16(sA_base + (stage * STAGE_HALFS + row * LDAH + c16 * 8) * 2,
                       g_Xh + (size_t)(m0 + row) * IDIM + kt * BKH + c16 * 8);
            cp_async16(sB_base + (stage * STAGE_HALFS + row * LDAH + c16 * 8) * 2,
                       g_Wh + (size_t)(n0 + row) * IDIM + kt * BKH + c16 * 8);
        }
    };

    loadAB(0, 0); CP_COMMIT();
    loadAB(1, 1); CP_COMMIT();

    for (int kt = 0; kt < KTILES; ++kt) {
        if (kt < KTILES - 1) { CP_WAIT(1); } else { CP_WAIT(0); }
        __syncthreads();

        if (kt + 2 < KTILES) { loadAB((kt + 2) % NSTG, kt + 2); CP_COMMIT(); }

        const __half* A = sA[kt % NSTG];
        const __half* B = sB[kt % NSTG];
#pragma unroll
        for (int kf = 0; kf < 2; ++kf) {
            const int k = kf * 16;
            uint32_t a[2][4], bf[8][2];
#pragma unroll
            for (int mi = 0; mi < 2; mi++) {
                int r = wm * 32 + mi * 16 + g;
                a[mi][0] = *(const uint32_t*)&A[r * LDAH + k + tg * 2];
                a[mi][1] = *(const uint32_t*)&A[(r + 8) * LDAH + k + tg * 2];
                a[mi][2] = *(const uint32_t*)&A[r * LDAH + k + 8 + tg * 2];
                a[mi][3] = *(const uint32_t*)&A[(r + 8) * LDAH + k + 8 + tg * 2];
            }
#pragma unroll
            for (int ni = 0; ni < 8; ni++) {
                int cc = wn * 64 + ni * 8 + g;
                bf[ni][0] = *(const uint32_t*)&B[cc * LDAH + k + tg * 2];
                bf[ni][1] = *(const uint32_t*)&B[cc * LDAH + k + 8 + tg * 2];
            }
#pragma unroll
            for (int mi = 0; mi < 2; mi++)
#pragma unroll
                for (int ni = 0; ni < 8; ni++) {
                    asm volatile(
                        "mma.sync.aligned.m16n8k16.row.col.f32.f16.f16.f32 "
                        "{%0,%1,%2,%3}, {%4,%5,%6,%7}, {%8,%9}, {%0,%1,%2,%3};"
                        : "+f"(c[mi][ni][0]), "+f"(c[mi][ni][1]),
                          "+f"(c[mi][ni][2]), "+f"(c[mi][ni][3])
                        : "r"(a[mi][0]), "r"(a[mi][1]), "r"(a[mi][2]), "r"(a[mi][3]),
                          "r"(bf[ni][0]), "r"(bf[ni][1]));
                }
        }
        __syncthreads();
    }

#pragma unroll
    for (int mi = 0; mi < 2; mi++) {
#pragma unroll
        for (int ni = 0; ni < 8; ni++) {
            int r     = m0 + wm * 32 + mi * 16 + g;
            int cbase = n0 + wn * 64 + ni * 8 + 2 * tg;
            __half2 v0 = __floats2half2_rn(c[mi][ni][0], c[mi][ni][1]);
            __half2 v1 = __floats2half2_rn(c[mi][ni][2], c[mi][ni][3]);
            *reinterpret_cast<__half2*>(g_uh + (size_t)r * HDIM + cbase)       = v0;
            *reinterpret_cast<__half2*>(g_uh + (size_t)(r + 8) * HDIM + cbase) = v1;
        }
    }
}

// ---------------------------------------------------------------------------
// Kernel 3: sequential scan over one 512-column h chunk.
// grid 256 CTAs x 64 thr: b = bid>>2, tile = bid&3.  Depth-32 prefetch ring.
// Memory-bound; designed to overlap the NEXT GEMM chunk (compute-bound).
// ---------------------------------------------------------------------------
#define SCAN_DEPTH 32

__global__ void scan_chunk_kernel(const float* __restrict__ hh, int h2_base) {
    const int b  = blockIdx.x >> 2;
    const int jt = blockIdx.x & 3;
    const int hc = h2_base + jt * 64 + threadIdx.x;          // half2 column
    const float a0 = hh[2 * hc];
    const float a1 = hh[2 * hc + 1];
    const __half2* p = reinterpret_cast<const __half2*>(g_uh)
                       + (size_t)b * (HDIM / 2) + hc;
    const size_t stride = (size_t)BATCH * HDIM / 2;          // 65536 half2/step

    __half2 buf[SCAN_DEPTH];
#pragma unroll
    for (int i = 0; i < SCAN_DEPTH; i++) buf[i] = p[(size_t)i * stride];

    float h0 = 0.0f, h1 = 0.0f;
    for (int s0 = 0; s0 < S_LEN; s0 += SCAN_DEPTH) {
#pragma unroll
        for (int i = 0; i < SCAN_DEPTH; i++) {
            float2 u = __half22float2(buf[i]);
            int ns = s0 + SCAN_DEPTH + i;
            if (ns < S_LEN) buf[i] = p[(size_t)ns * stride];
            h0 = fabsf(fmaf(a0, h0, u.x));
            h1 = fabsf(fmaf(a1, h1, u.y));
        }
    }
    *reinterpret_cast<float2*>(g_h + 2 * (b * (HDIM / 2) + hc)) =
        make_float2(h0, h1);
}

// ---------------------------------------------------------------------------
// Kernel 4/5: split-K output GEMM (KSLICES=32) + reduce
// ---------------------------------------------------------------------------
#define KSLICES 32

__global__ __launch_bounds__(256) void out_partial_kernel(const float* __restrict__ W_ho) {
    __shared__ float sh[64][65];
    __shared__ float sw[64][65];
    const int tid = threadIdx.x;
    const int tx = tid & 15, ty = tid >> 4;
    const int o0 = blockIdx.x * 64;
    const int ks = blockIdx.y;
    const int kbase = ks * 64;

    float acc[4][4];
#pragma unroll
    for (int i = 0; i < 4; i++)
#pragma unroll
        for (int j = 0; j < 4; j++) acc[i][j] = 0.0f;

#pragma unroll
    for (int i = 0; i < 16; i++) {
        int lin = tid + i * 256;
        int row = lin >> 6, col = lin & 63;
        sh[row][col] = g_h[(size_t)row * HDIM + kbase + col];
        sw[row][col] = W_ho[(size_t)(o0 + row) * HDIM + kbase + col];
    }
    __syncthreads();
#pragma unroll 8
    for (int k = 0; k < 64; k++) {
        float av[4], bv[4];
#pragma unroll
        for (int i = 0; i < 4; i++) av[i] = sh[ty * 4 + i][k];
#pragma unroll
        for (int j = 0; j < 4; j++) bv[j] = sw[tx * 4 + j][k];
#pragma unroll
        for (int i = 0; i < 4; i++)
#pragma unroll
            for (int j = 0; j < 4; j++) acc[i][j] = fmaf(av[i], bv[j], acc[i][j]);
    }

#pragma unroll
    for (int i = 0; i < 4; i++)
#pragma unroll
        for (int j = 0; j < 4; j++) {
            int bb = ty * 4 + i;
            int o  = o0 + tx * 4 + j;
            g_part[(size_t)ks * (BATCH * ODIM) + bb * ODIM + o] = acc[i][j];
        }
}

__global__ void out_reduce_kernel(const float* __restrict__ b_ho, float* __restrict__ Y) {
    int i = blockIdx.x * blockDim.x + threadIdx.x;
    float s = b_ho[i & (ODIM - 1)];
#pragma unroll
    for (int k = 0; k < KSLICES; k++) s += g_part[(size_t)k * (BATCH * ODIM) + i];
    Y[i] = s;
}

// ---------------------------------------------------------------------------
// Launch — 4 GEMM N-chunks serial on the main stream; after each, fork a
// side-stream scan for that chunk (graph fork/join via events).  The scans
// (DRAM-bound) overlap the next GEMM chunk (issue-bound).  Join before the
// output GEMM.
// ---------------------------------------------------------------------------
#define NCHUNK 4
#define NTILES_PER_CHUNK (HDIM / BN / NCHUNK)   // 4

extern "C" void kernel_launch(void* const* d_in, const int* in_sizes, int n_in,
                              void* d_out, int out_size) {
    const float* X    = (const float*)d_in[0];   // [1024,64,512]
    const float* W_ih = (const float*)d_in[1];   // [2048,512]
    const float* hh   = (const float*)d_in[2];   // [2048]
    const float* W_ho = (const float*)d_in[3];   // [512,2048]
    const float* b_ho = (const float*)d_in[4];   // [512]
    float* Y = (float*)d_out;                    // [64,512]

    // Lazily created side stream + events (host handles only; no dev mem)
    static cudaStream_t s2 = nullptr;
    static cudaEvent_t evG[NCHUNK], evJoin;
    if (s2 == nullptr) {
        cudaStreamCreateWithFlags(&s2, cudaStreamNonBlocking);
        for (int c = 0; c < NCHUNK; c++)
            cudaEventCreateWithFlags(&evG[c], cudaEventDisableTiming);
        cudaEventCreateWithFlags(&evJoin, cudaEventDisableTiming);
    }

    // 1) fused fp16 conversion prepass (X and W)
    cvt_kernel<<<(NX_H8 + NW_H8) / 256, 256>>>((const float4*)X,
                                               (const float4*)W_ih);

    // 2/3) GEMM chunks on main stream; scan of each finished chunk forked
    //      onto s2, overlapping the next GEMM chunk.
    for (int c = 0; c < NCHUNK; c++) {
        dim3 ggrid(NTILES_PER_CHUNK, MTOT / BM);        // (4, 512)
        gemm_u_kernel<<<ggrid, 256>>>(c * NTILES_PER_CHUNK * BN);
        cudaEventRecord(evG[c], 0);
        cudaStreamWaitEvent(s2, evG[c], 0);
        scan_chunk_kernel<<<BATCH * 4, 64, 0, s2>>>(hh, c * (512 / 2));
    }
    cudaEventRecord(evJoin, s2);
    cudaStreamWaitEvent(0, evJoin, 0);

    // 4) output GEMM (split-K) + reduce
    dim3 ogrid(ODIM / 64, KSLICES);
    out_partial_kernel<<<ogrid, 256>>>(W_ho);
    out_reduce_kernel<<<(BATCH * ODIM) / 256, 256>>>(b_ho, Y);
}

// round 10
// speedup vs baseline: 1.3865x; 1.3865x over previous
#include <cuda_runtime.h>
#include <cuda_fp16.h>
#include <cstdint>

// Problem dims
#define S_LEN 1024
#define BATCH 64
#define IDIM  512
#define HDIM  2048
#define ODIM  512
#define MTOT  (S_LEN * BATCH)   // 65536

// ---------------------------------------------------------------------------
// Device scratch (no cudaMalloc allowed)
// ---------------------------------------------------------------------------
__device__ __half g_Xh[(size_t)MTOT * IDIM];        // 64 MB   fp16 X
__device__ __half g_Wh[(size_t)HDIM * IDIM];        // 2 MB    fp16 W_ih
__device__ __half g_uh[(size_t)MTOT * HDIM];        // 256 MB  u (fp16)
__device__ float  g_h [(size_t)BATCH * HDIM];       // 512 KB  h_final[b][h]
__device__ float  g_part[(size_t)32 * BATCH * ODIM];// 4 MB    split-K partials

// ---------------------------------------------------------------------------
// Helpers
// ---------------------------------------------------------------------------
__device__ __forceinline__ void cp_async16(uint32_t saddr, const void* gptr) {
    asm volatile("cp.async.cg.shared.global [%0], [%1], 16;\n"
                 :: "r"(saddr), "l"(gptr) : "memory");
}
#define CP_COMMIT() asm volatile("cp.async.commit_group;\n" ::: "memory")
#define CP_WAIT(N)  asm volatile("cp.async.wait_group %0;\n" :: "n"(N) : "memory")

#define LDSM_X4(r0, r1, r2, r3, addr) \
    asm volatile("ldmatrix.sync.aligned.m8n8.x4.shared.b16 {%0,%1,%2,%3}, [%4];" \
                 : "=r"(r0), "=r"(r1), "=r"(r2), "=r"(r3) : "r"(addr))

struct alignas(16) H8 { __half2 a, b, c, d; };

// ---------------------------------------------------------------------------
// Kernel 1: fused fp32 -> fp16 conversion prepass (X then W in one grid)
// ---------------------------------------------------------------------------
#define NX_H8 (MTOT * IDIM / 8)          // 4,194,304
#define NW_H8 (HDIM * IDIM / 8)          // 131,072

__global__ void cvt_kernel(const float4* __restrict__ X,
                           const float4* __restrict__ W) {
    int i = blockIdx.x * blockDim.x + threadIdx.x;
    const float4* src;
    H8* dst;
    int j;
    if (i < NX_H8) {
        src = X;  dst = reinterpret_cast<H8*>(g_Xh);  j = i;
    } else {
        src = W;  dst = reinterpret_cast<H8*>(g_Wh);  j = i - NX_H8;
    }
    float4 v0 = src[2 * j], v1 = src[2 * j + 1];
    H8 o;
    o.a = __floats2half2_rn(v0.x, v0.y);
    o.b = __floats2half2_rn(v0.z, v0.w);
    o.c = __floats2half2_rn(v1.x, v1.y);
    o.d = __floats2half2_rn(v1.z, v1.w);
    dst[j] = o;
}

// ---------------------------------------------------------------------------
// Kernel 2: u = Xh @ Wh^T via mma.sync.m16n8k16.
// R9 ncu showed tensor=42%, L1=45%: the limiter was 24 bank-conflicted
// LDS.32 per kf-step.  Replaced with 6 conflict-free ldmatrix.x4 per
// kf-step (A: 1 per mi; B: 1 per ni-pair).  With LDAH=40 the 8 rows of
// each 8x8 matrix start at banks {0,20,8,28,16,4,24,12} and their 16B
// spans tile all 32 banks exactly once.
// CTA tile 128x128, BK=32, 3-stage cp.async pipeline, 8 warps (4x2).
// ---------------------------------------------------------------------------
#define BM 128
#define BN 128
#define BKH 32
#define KTILES (IDIM / BKH)        // 16
#define NSTG 3
#define LDAH 40
#define STAGE_HALFS (BM * LDAH)
#define STAGE_BYTES (STAGE_HALFS * 2)

__global__ __launch_bounds__(256, 2) void gemm_u_kernel() {
    __shared__ __half sA[NSTG][STAGE_HALFS];
    __shared__ __half sB[NSTG][STAGE_HALFS];

    const int tid  = threadIdx.x;
    const int lane = tid & 31;
    const int warp = tid >> 5;
    const int wm   = warp >> 1;   // 0..3
    const int wn   = warp & 1;    // 0..1
    const int g    = lane >> 2;   // 0..7
    const int tg   = lane & 3;    // 0..3

    const int m0 = blockIdx.y * BM;
    const int n0 = blockIdx.x * BN;

    const uint32_t sA_base = (uint32_t)__cvta_generic_to_shared(&sA[0][0]);
    const uint32_t sB_base = (uint32_t)__cvta_generic_to_shared(&sB[0][0]);

    // Per-lane ldmatrix byte offsets within a stage.
    // A-frag (m16k16): sel0 (r0+ro, k) sel1 (r0+8+ro, k) sel2 (r0+ro, k+8)
    //                  sel3 (r0+8+ro, k+8)
    // B-pair (n16k16): sel0 (c0+ro, k) sel1 (c0+ro, k+8) sel2 (c0+8+ro, k)
    //                  sel3 (c0+8+ro, k+8)
    const int ro  = lane & 7;
    const int sel = lane >> 3;
    uint32_t offA[2], offB[4];
#pragma unroll
    for (int mi = 0; mi < 2; mi++) {
        int rowA = wm * 32 + mi * 16 + (sel & 1) * 8 + ro;
        int colA = (sel >> 1) * 8;
        offA[mi] = (uint32_t)(rowA * LDAH + colA) * 2;
    }
#pragma unroll
    for (int p = 0; p < 4; p++) {
        int rowB = wn * 64 + p * 16 + (sel >> 1) * 8 + ro;
        int colB = (sel & 1) * 8;
        offB[p] = (uint32_t)(rowB * LDAH + colB) * 2;
    }

    float c[2][8][4];
#pragma unroll
    for (int mi = 0; mi < 2; mi++)
#pragma unroll
        for (int ni = 0; ni < 8; ni++)
#pragma unroll
            for (int r = 0; r < 4; r++) c[mi][ni][r] = 0.0f;

    auto loadAB = [&](int stage, int kt) {
#pragma unroll
        for (int i = 0; i < 2; i++) {
            int lin = tid + i * 256;
            int row = lin >> 2, c16 = lin & 3;
            cp_async16(sA_base + stage * STAGE_BYTES + (row * LDAH + c16 * 8) * 2,
                       g_Xh + (size_t)(m0 + row) * IDIM + kt * BKH + c16 * 8);
            cp_async16(sB_base + stage * STAGE_BYTES + (row * LDAH + c16 * 8) * 2,
                       g_Wh + (size_t)(n0 + row) * IDIM + kt * BKH + c16 * 8);
        }
    };

    loadAB(0, 0); CP_COMMIT();
    loadAB(1, 1); CP_COMMIT();

    for (int kt = 0; kt < KTILES; ++kt) {
        if (kt < KTILES - 1) { CP_WAIT(1); } else { CP_WAIT(0); }
        __syncthreads();

        if (kt + 2 < KTILES) { loadAB((kt + 2) % NSTG, kt + 2); CP_COMMIT(); }

        const uint32_t aStage = sA_base + (kt % NSTG) * STAGE_BYTES;
        const uint32_t bStage = sB_base + (kt % NSTG) * STAGE_BYTES;
#pragma unroll
        for (int kf = 0; kf < 2; ++kf) {
            const uint32_t kbyte = kf * 32;   // 16 halves
            uint32_t a[2][4], bf[8][2];
#pragma unroll
            for (int mi = 0; mi < 2; mi++)
                LDSM_X4(a[mi][0], a[mi][1], a[mi][2], a[mi][3],
                        aStage + offA[mi] + kbyte);
#pragma unroll
            for (int p = 0; p < 4; p++)
                LDSM_X4(bf[2 * p][0], bf[2 * p][1], bf[2 * p + 1][0],
                        bf[2 * p + 1][1], bStage + offB[p] + kbyte);
#pragma unroll
            for (int mi = 0; mi < 2; mi++)
#pragma unroll
                for (int ni = 0; ni < 8; ni++) {
                    asm volatile(
                        "mma.sync.aligned.m16n8k16.row.col.f32.f16.f16.f32 "
                        "{%0,%1,%2,%3}, {%4,%5,%6,%7}, {%8,%9}, {%0,%1,%2,%3};"
                        : "+f"(c[mi][ni][0]), "+f"(c[mi][ni][1]),
                          "+f"(c[mi][ni][2]), "+f"(c[mi][ni][3])
                        : "r"(a[mi][0]), "r"(a[mi][1]), "r"(a[mi][2]), "r"(a[mi][3]),
                          "r"(bf[ni][0]), "r"(bf[ni][1]));
                }
        }
        __syncthreads();
    }

#pragma unroll
    for (int mi = 0; mi < 2; mi++) {
#pragma unroll
        for (int ni = 0; ni < 8; ni++) {
            int r     = m0 + wm * 32 + mi * 16 + g;
            int cbase = n0 + wn * 64 + ni * 8 + 2 * tg;
            __half2 v0 = __floats2half2_rn(c[mi][ni][0], c[mi][ni][1]);
            __half2 v1 = __floats2half2_rn(c[mi][ni][2], c[mi][ni][3]);
            *reinterpret_cast<__half2*>(g_uh + (size_t)r * HDIM + cbase)       = v0;
            *reinterpret_cast<__half2*>(g_uh + (size_t)(r + 8) * HDIM + cbase) = v1;
        }
    }
}

// ---------------------------------------------------------------------------
// Kernel 3: sequential scan h = |u_t + hh*h|, fp16 u, 2 channels/thread.
// 1024 CTAs x 64 thr, depth-32 prefetch ring (8 MB in flight).
// ---------------------------------------------------------------------------
#define SCAN_DEPTH 32

__global__ void scan_kernel(const float* __restrict__ hh) {
    const int ch2 = blockIdx.x * blockDim.x + threadIdx.x;   // half2 index
    const int hpair = (2 * ch2) & (HDIM - 1);
    const float a0 = hh[hpair];
    const float a1 = hh[hpair + 1];
    const __half2* p = reinterpret_cast<const __half2*>(g_uh) + ch2;
    const size_t stride = (size_t)BATCH * HDIM / 2;          // 65536 half2s

    __half2 buf[SCAN_DEPTH];
#pragma unroll
    for (int i = 0; i < SCAN_DEPTH; i++) buf[i] = p[(size_t)i * stride];

    float h0 = 0.0f, h1 = 0.0f;
    for (int s0 = 0; s0 < S_LEN; s0 += SCAN_DEPTH) {
#pragma unroll
        for (int i = 0; i < SCAN_DEPTH; i++) {
            float2 u = __half22float2(buf[i]);
            int ns = s0 + SCAN_DEPTH + i;
            if (ns < S_LEN) buf[i] = p[(size_t)ns * stride];
            h0 = fabsf(fmaf(a0, h0, u.x));
            h1 = fabsf(fmaf(a1, h1, u.y));
        }
    }
    *reinterpret_cast<float2*>(g_h + 2 * ch2) = make_float2(h0, h1);
}

// ---------------------------------------------------------------------------
// Kernel 4/5: split-K output GEMM (KSLICES=32) + reduce
// ---------------------------------------------------------------------------
#define KSLICES 32

__global__ __launch_bounds__(256) void out_partial_kernel(const float* __restrict__ W_ho) {
    __shared__ float sh[64][65];
    __shared__ float sw[64][65];
    const int tid = threadIdx.x;
    const int tx = tid & 15, ty = tid >> 4;
    const int o0 = blockIdx.x * 64;
    const int ks = blockIdx.y;
    const int kbase = ks * 64;

    float acc[4][4];
#pragma unroll
    for (int i = 0; i < 4; i++)
#pragma unroll
        for (int j = 0; j < 4; j++) acc[i][j] = 0.0f;

#pragma unroll
    for (int i = 0; i < 16; i++) {
        int lin = tid + i * 256;
        int row = lin >> 6, col = lin & 63;
        sh[row][col] = g_h[(size_t)row * HDIM + kbase + col];
        sw[row][col] = W_ho[(size_t)(o0 + row) * HDIM + kbase + col];
    }
    __syncthreads();
#pragma unroll 8
    for (int k = 0; k < 64; k++) {
        float av[4], bv[4];
#pragma unroll
        for (int i = 0; i < 4; i++) av[i] = sh[ty * 4 + i][k];
#pragma unroll
        for (int j = 0; j < 4; j++) bv[j] = sw[tx * 4 + j][k];
#pragma unroll
        for (int i = 0; i < 4; i++)
#pragma unroll
            for (int j = 0; j < 4; j++) acc[i][j] = fmaf(av[i], bv[j], acc[i][j]);
    }

#pragma unroll
    for (int i = 0; i < 4; i++)
#pragma unroll
        for (int j = 0; j < 4; j++) {
            int bb = ty * 4 + i;
            int o  = o0 + tx * 4 + j;
            g_part[(size_t)ks * (BATCH * ODIM) + bb * ODIM + o] = acc[i][j];
        }
}

__global__ void out_reduce_kernel(const float* __restrict__ b_ho, float* __restrict__ Y) {
    int i = blockIdx.x * blockDim.x + threadIdx.x;
    float s = b_ho[i & (ODIM - 1)];
#pragma unroll
    for (int k = 0; k < KSLICES; k++) s += g_part[(size_t)k * (BATCH * ODIM) + i];
    Y[i] = s;
}

// ---------------------------------------------------------------------------
// Launch
// ---------------------------------------------------------------------------
extern "C" void kernel_launch(void* const* d_in, const int* in_sizes, int n_in,
                              void* d_out, int out_size) {
    const float* X    = (const float*)d_in[0];   // [1024,64,512]
    const float* W_ih = (const float*)d_in[1];   // [2048,512]
    const float* hh   = (const float*)d_in[2];   // [2048]
    const float* W_ho = (const float*)d_in[3];   // [512,2048]
    const float* b_ho = (const float*)d_in[4];   // [512]
    float* Y = (float*)d_out;                    // [64,512]

    // 1) fused fp16 conversion prepass (X and W)
    cvt_kernel<<<(NX_H8 + NW_H8) / 256, 256>>>((const float4*)X,
                                               (const float4*)W_ih);

    // 2) big GEMM u = Xh @ Wh^T (fp16 mma, ldmatrix fragments)
    dim3 ggrid(HDIM / BN, MTOT / BM);  // (16, 512) x-major: N-tiles share A in L2
    gemm_u_kernel<<<ggrid, 256>>>();

    // 3) sequential scan
    scan_kernel<<<(BATCH * HDIM / 2) / 64, 64>>>(hh);

    // 4) output GEMM (split-K) + reduce
    dim3 ogrid(ODIM / 64, KSLICES);
    out_partial_kernel<<<ogrid, 256>>>(W_ho);
    out_reduce_kernel<<<(BATCH * ODIM) / 256, 256>>>(b_ho, Y);
}